// round 7
// baseline (speedup 1.0000x reference)
#include <cuda_runtime.h>
#include <cstdint>
#include <cstddef>

#define DM 63
#define DD 64
#define NR_MAX 256
#define B_MAX 2048
#define TMAIN 128
#define TILE  128
#define XSTR  68   // padded row stride in floats (bank-conflict floor)

// ---- scratch (static __device__ globals; no runtime allocation) ----
__device__ float g_Wg[2][(size_t)NR_MAX * DM * DD];   // gelu(W): [side][r][j][k], k=63 pad -> 0
__device__ float g_Wt[2][(size_t)NR_MAX * DM * DD];   // W^T, padded: [side][r][c][e], e=0 -> 0
__device__ float g_off[2][NR_MAX * DD];               // mobius offset per relation
__device__ float g_off2[2][NR_MAX];                   // sum(off^2)
__device__ float g_p63[NR_MAX * DD];                  // tail: unscaled last col of P, [0]=0
__device__ float g_ofu[NR_MAX * DD];                  // tail: W @ off_sp, [0]=off0
__device__ float g_th[B_MAX * DD];                    // transformed head per batch row
__device__ float g_ttl[B_MAX * DD];                   // tail: W_t @ th_sp per b, [0]=0
__device__ float g_thb[B_MAX];                        // tanh(bias_head[u])

__device__ __forceinline__ float gelu_exact(float x) {
    return 0.5f * x * (1.0f + erff(x * 0.70710678118654752f));
}

// block reduction over 64 threads (2 warps)
__device__ __forceinline__ float bred64(float v, volatile float* wsum, int lane, int wid) {
    #pragma unroll
    for (int o = 16; o; o >>= 1) v += __shfl_down_sync(0xffffffffu, v, o);
    if (lane == 0) wsum[wid] = v;
    __syncthreads();
    float r = wsum[0] + wsum[1];
    __syncthreads();
    return r;
}

// ============================================================================
// K0: fully-parallel gelu of all relation weights
// ============================================================================
__global__ void k_gelu(const float* __restrict__ Wh, const float* __restrict__ Wtt, int NR)
{
    int i = blockIdx.x * blockDim.x + threadIdx.x;
    int total = 2 * NR * DM * DD;
    if (i >= total) return;
    int k  = i & (DD - 1);
    int j  = (i >> 6) % DM;
    int rs = i / (DM * DD);
    int r  = rs % NR;
    int side = rs / NR;
    float v = 0.0f;
    if (k < DM) {
        const float* src = side ? Wtt : Wh;
        v = gelu_exact(src[(size_t)r * DM * DM + j * DM + k]);
    }
    g_Wg[side][(size_t)r * DM * DD + j * DD + k] = v;
}

// ============================================================================
// K1: per-relation precompute. grid (NR, 2), block 64.
// ============================================================================
__global__ void k_rel(const float* __restrict__ rch, const float* __restrict__ dirh,
                      const float* __restrict__ rct, const float* __restrict__ dirt,
                      const float* __restrict__ fsh, const float* __restrict__ fst)
{
    int r    = blockIdx.x;
    int side = blockIdx.y;
    const float* rc = side ? rct  : rch;
    const float* dw = side ? dirt : dirh;
    float fs        = side ? fst[0] : fsh[0];

    __shared__ __align__(16) float Wg[DM * DD];
    __shared__ float inv2s[DM];
    __shared__ float ws[DD];
    __shared__ float wsum[2];

    int tid = threadIdx.x;
    int lane = tid & 31, wid = tid >> 5;

    {
        const float4* src = (const float4*)&g_Wg[side][(size_t)r * DM * DD];
        float4* dst = (float4*)Wg;
        for (int i = tid; i < DM * DD / 4; i += 64) dst[i] = src[i];
    }
    __syncthreads();
    if (tid < DM) {
        const float* row = Wg + tid * DD;
        float s0 = 0, s1 = 0, s2 = 0, s3 = 0;
        #pragma unroll
        for (int k = 0; k < 60; k += 4) {
            s0 = fmaf(row[k    ], row[k    ], s0);
            s1 = fmaf(row[k + 1], row[k + 1], s1);
            s2 = fmaf(row[k + 2], row[k + 2], s2);
            s3 = fmaf(row[k + 3], row[k + 3], s3);
        }
        s0 = fmaf(row[60], row[60], s0);
        s1 = fmaf(row[61], row[61], s1);
        s2 = fmaf(row[62], row[62], s2);
        inv2s[tid] = 2.0f / ((s0 + s1) + (s2 + s3));
    }
    __syncthreads();

    float prow[DM];
    #pragma unroll
    for (int k = 0; k < DM; k++) prow[k] = (k == tid) ? 1.0f : 0.0f;

    for (int j = 0; j < DM; j++) {
        const float* wj = Wg + j * DD;
        float a0 = 0, a1 = 0, a2 = 0, a3 = 0;
        #pragma unroll
        for (int k = 0; k < 60; k += 4) {
            a0 = fmaf(prow[k    ], wj[k    ], a0);
            a1 = fmaf(prow[k + 1], wj[k + 1], a1);
            a2 = fmaf(prow[k + 2], wj[k + 2], a2);
            a3 = fmaf(prow[k + 3], wj[k + 3], a3);
        }
        a0 = fmaf(prow[60], wj[60], a0);
        a1 = fmaf(prow[61], wj[61], a1);
        a2 = fmaf(prow[62], wj[62], a2);
        float coef = ((a0 + a1) + (a2 + a3)) * inv2s[j];
        #pragma unroll
        for (int k = 0; k < DM; k++) prow[k] = fmaf(-coef, wj[k], prow[k]);
    }

    float p63v = prow[62];
    prow[62] *= fs;

    {
        float* base = &g_Wt[side][(size_t)r * DM * DD];
        if (tid < DM) {
            #pragma unroll
            for (int c = 0; c < DM; c++) base[(size_t)c * DD + 1 + tid] = prow[c];
        } else {
            for (int c = 0; c < DM; c++) base[(size_t)c * DD] = 0.0f;
        }
    }

    // ---- offset = expmap(c, 0.1 * normalize(d + <c,d> c)) ----
    float cv = rc[r * DD + tid];
    float dv = dw[r * DD + tid];
    float inner = bred64(cv * dv, wsum, lane, wid);
    float tv = fmaf(inner, cv, dv);
    float tn2 = bred64(tv * tv, wsum, lane, wid);
    tv = tv / (sqrtf(tn2) + 1e-6f);
    float uv = 0.1f * tv;
    float su2 = bred64(uv * uv, wsum, lane, wid);
    ws[tid] = uv;
    __syncthreads();
    float u0 = ws[0];
    float lin = su2 - 2.0f * u0 * u0;
    float nrm = fminf(sqrtf(fmaxf(lin, 1e-8f)), 2.5f);
    float off = coshf(nrm) * cv + sinhf(nrm) * uv / nrm;
    g_off[side][r * DD + tid] = off;
    float off2 = bred64(off * off, wsum, lane, wid);
    if (tid == 0) g_off2[side][r] = off2;

    if (side == 1) {
        __syncthreads();
        ws[tid] = off;
        __syncthreads();
        if (tid < DM) {
            float a0 = 0, a1 = 0, a2 = 0, a3 = 0;
            #pragma unroll
            for (int c = 0; c < 60; c += 4) {
                a0 = fmaf(prow[c    ], ws[c + 1], a0);
                a1 = fmaf(prow[c + 1], ws[c + 2], a1);
                a2 = fmaf(prow[c + 2], ws[c + 3], a2);
                a3 = fmaf(prow[c + 3], ws[c + 4], a3);
            }
            a0 = fmaf(prow[60], ws[61], a0);
            a1 = fmaf(prow[61], ws[62], a1);
            a2 = fmaf(prow[62], ws[63], a2);
            g_ofu[r * DD + 1 + tid] = (a0 + a1) + (a2 + a3);
            g_p63[r * DD + 1 + tid] = p63v;
        } else {
            g_ofu[r * DD] = ws[0];
            g_p63[r * DD] = 0.0f;
        }
    }
}

// ============================================================================
// K2: head transform + per-b tail projection. grid B, block 64.
// ============================================================================
__global__ void k_th(const float* __restrict__ ent, const float* __restrict__ bias_head,
                     const int* __restrict__ u_idx, const int* __restrict__ r_idx)
{
    int b = blockIdx.x;
    int tid = threadIdx.x;
    int lane = tid & 31, wid = tid >> 5;
    __shared__ float xs[DD];
    __shared__ float wsum[2];
    int u = u_idx[b];
    int r = r_idx[b];
    xs[tid] = ent[(size_t)u * DD + tid];
    __syncthreads();
    float yv;
    if (tid == 0) {
        yv = xs[0];
    } else {
        const float* wrow = &g_Wt[0][((size_t)r * DM + (tid - 1)) * DD];
        float a0 = 0, a1 = 0, a2 = 0, a3 = 0;
        #pragma unroll
        for (int e = 0; e < DD; e += 4) {
            a0 = fmaf(xs[e    ], wrow[e    ], a0);
            a1 = fmaf(xs[e + 1], wrow[e + 1], a1);
            a2 = fmaf(xs[e + 2], wrow[e + 2], a2);
            a3 = fmaf(xs[e + 3], wrow[e + 3], a3);
        }
        yv = (a0 + a1) + (a2 + a3);
    }
    float offv = g_off[0][r * DD + tid];
    float x2 = bred64(yv * yv, wsum, lane, wid);
    float xy = bred64(yv * offv, wsum, lane, wid);
    float y2 = g_off2[0][r];
    float A   = 1.0f + 2.0f * xy + y2;
    float Bc  = 1.0f - x2;
    float den = 1.0f + 2.0f * xy + x2 * y2 + 1e-15f;
    float th  = fmaf(A, yv, Bc * offv) / den;
    g_th[b * DD + tid] = th;
    if (tid == 0) g_thb[b] = tanhf(bias_head[u]);

    __syncthreads();
    xs[tid] = th;
    __syncthreads();
    const float* base1 = &g_Wt[1][(size_t)r * DM * DD];
    if (tid < DM) {
        float a0 = 0, a1 = 0, a2 = 0, a3 = 0;
        #pragma unroll 4
        for (int c = 0; c < 60; c += 4) {
            a0 = fmaf(base1[(c    ) * DD + 1 + tid], xs[c + 1], a0);
            a1 = fmaf(base1[(c + 1) * DD + 1 + tid], xs[c + 2], a1);
            a2 = fmaf(base1[(c + 2) * DD + 1 + tid], xs[c + 3], a2);
            a3 = fmaf(base1[(c + 3) * DD + 1 + tid], xs[c + 4], a3);
        }
        a0 = fmaf(base1[60 * DD + 1 + tid], xs[61], a0);
        a1 = fmaf(base1[61 * DD + 1 + tid], xs[62], a1);
        a2 = fmaf(base1[62 * DD + 1 + tid], xs[63], a2);
        g_ttl[b * DD + 1 + tid] = (a0 + a1) + (a2 + a3);
    } else {
        g_ttl[b * DD] = 0.0f;
    }
}

// ============================================================================
// K3: main scoring. grid B, block 128. Cooperative coalesced gather:
//   load phase — 16 consecutive lanes fetch one ent row (4 lines per LDG.128,
//   the minimum), staged to smem with stride 68 (crossbar-floor bank layout);
//   compute phase — thread t <-> tail t, 3 smem dots + algebraic epilogue.
// ============================================================================
__global__ void __launch_bounds__(TMAIN) k_main(
    const float* __restrict__ ent, const float* __restrict__ bias_tail,
    const int* __restrict__ r_idx, const int* __restrict__ v_idx,
    const float* __restrict__ fst,
    float* __restrict__ out, int N)
{
    __shared__ __align__(16) float xs[TILE * XSTR];   // 34816 B
    __shared__ int   vs[TILE];
    __shared__ float pv[DD], ov[DD], tl[DD];
    __shared__ float off_f[DD], th_f[DD];

    int b = blockIdx.x;
    int tid = threadIdx.x;
    int r = r_idx[b];

    if (tid < DD) {
        pv[tid]    = g_p63[r * DD + tid];
        ov[tid]    = g_ofu[r * DD + tid];
        tl[tid]    = g_ttl[b * DD + tid];
        off_f[tid] = g_off[1][r * DD + tid];
        th_f[tid]  = g_th[b * DD + tid];
    }
    float off2 = g_off2[1][r];
    float thb  = g_thb[b];
    float fs   = fst[0];
    float fsm1 = fs * fs - 1.0f;
    __syncthreads();

    float O2m = 0, OTm = 0, T2m = 0;
    #pragma unroll
    for (int c = 1; c < DD; c++) {
        float o = off_f[c], t = th_f[c];
        O2m = fmaf(o, o, O2m);
        OTm = fmaf(o, t, OTm);
        T2m = fmaf(t, t, T2m);
    }
    float off0 = off_f[0], th0 = th_f[0];

    const float4* pv4 = (const float4*)pv;
    const float4* ov4 = (const float4*)ov;
    const float4* tl4 = (const float4*)tl;

    for (int tbase = 0; tbase < N; tbase += TILE) {
        // stage v indices (coalesced)
        int nt = min(TILE, N - tbase);
        if (tid < TILE) vs[tid] = (tid < nt) ? v_idx[b * N + tbase + tid] : 0;
        __syncthreads();

        // load phase: 2048 float4, 16 lanes per row -> 4 lines per LDG.128
        #pragma unroll 8
        for (int i = 0; i < 16; i++) {
            int f  = i * TMAIN + tid;        // 0..2047
            int tt = f >> 4;                  // tail slot 0..127
            int q  = f & 15;                  // float4 index in row
            const float4* src = (const float4*)(ent + (size_t)vs[tt] * DD) + q;
            *(float4*)&xs[tt * XSTR + q * 4] = *src;
        }
        __syncthreads();

        if (tid < nt) {
            int v = vs[tid];
            const float4* xr = (const float4*)&xs[tid * XSTR];

            float s1a = 0, s1b = 0, s2a = 0, s2b = 0, s3a = 0, s3b = 0;
            float y0 = xs[tid * XSTR];
            #pragma unroll
            for (int q = 0; q < 16; q++) {
                float4 x4 = xr[q];
                float4 p4 = pv4[q];
                float4 o4 = ov4[q];
                float4 t4 = tl4[q];
                s1a = fmaf(x4.x, p4.x, s1a);  s1b = fmaf(x4.y, p4.y, s1b);
                s1a = fmaf(x4.z, p4.z, s1a);  s1b = fmaf(x4.w, p4.w, s1b);
                s2a = fmaf(x4.x, o4.x, s2a);  s2b = fmaf(x4.y, o4.y, s2b);
                s2a = fmaf(x4.z, o4.z, s2a);  s2b = fmaf(x4.w, o4.w, s2b);
                s3a = fmaf(x4.x, t4.x, s3a);  s3b = fmaf(x4.y, t4.y, s3b);
                s3a = fmaf(x4.z, t4.z, s3a);  s3b = fmaf(x4.w, t4.w, s3b);
            }
            float s1  = s1a + s1b;          // x . p63
            float syo = s2a + s2b;          // includes x0*off0
            float syt = s3a + s3b;          // c>=1 only

            float syy_m = fmaf(fsm1, s1 * s1, fmaf(y0, y0, -1.0f));  // syy - y0^2
            float syy   = syy_m + y0 * y0;

            float A   = 1.0f + 2.0f * syo + off2;
            float Bv  = 1.0f - syy;
            float den = 1.0f + 2.0f * syo + syy * off2 + 1e-15f;
            float rd  = 1.0f / den;
            float a   = A * rd, bs = Bv * rd;
            float d0  = fmaf(a, y0, fmaf(bs, off0, -th0));
            float cross = fmaf(bs, syo - y0 * off0, -syt);
            float bterm = fmaf(bs, fmaf(bs, O2m, -2.0f * OTm), T2m);
            float sum1  = fmaf(a * a, syy_m, fmaf(2.0f * a, cross, bterm));
            float mkv   = sum1 - d0 * d0;

            float btv = tanhf(bias_tail[v]);
            out[(size_t)b * N + tbase + tid] = 8.0f - mkv + thb + btv;
        }
        __syncthreads();
    }
}

// ============================================================================
extern "C" void kernel_launch(void* const* d_in, const int* in_sizes, int n_in,
                              void* d_out, int out_size)
{
    (void)n_in; (void)out_size;
    const float* ent  = (const float*)d_in[0];
    const float* Wh   = (const float*)d_in[1];
    const float* Wtt  = (const float*)d_in[2];
    const float* rch  = (const float*)d_in[3];
    const float* dirh = (const float*)d_in[4];
    const float* rct  = (const float*)d_in[5];
    const float* dirt = (const float*)d_in[6];
    const float* bh   = (const float*)d_in[7];
    const float* bt   = (const float*)d_in[8];
    const float* fsh  = (const float*)d_in[9];
    const float* fst  = (const float*)d_in[10];
    const int* u_idx  = (const int*)d_in[11];
    const int* r_idx  = (const int*)d_in[12];
    const int* v_idx  = (const int*)d_in[13];
    float* out = (float*)d_out;

    int NR = in_sizes[3] / DD;       // 237
    int B  = in_sizes[11];           // 1024
    int N  = in_sizes[13] / B;       // 512

    int total_g = 2 * NR * DM * DD;
    k_gelu<<<(total_g + 255) / 256, 256>>>(Wh, Wtt, NR);
    k_rel<<<dim3(NR, 2), 64>>>(rch, dirh, rct, dirt, fsh, fst);
    k_th<<<B, 64>>>(ent, bh, u_idx, r_idx);
    k_main<<<B, TMAIN>>>(ent, bt, r_idx, v_idx, fst, out, N);
}

// round 8
// speedup vs baseline: 1.2006x; 1.2006x over previous
#include <cuda_runtime.h>
#include <cstdint>
#include <cstddef>

#define DM 63
#define DD 64
#define NR_MAX 256
#define B_MAX 2048
#define TMAIN 128
#define TILE  128
#define XSTR  68   // padded row stride in floats (bank-conflict floor)

// ---- scratch (static __device__ globals; no runtime allocation) ----
__device__ float g_Wg[2][(size_t)NR_MAX * DM * DD];   // gelu(W): [side][r][j][k], k=63 pad -> 0
__device__ float g_Wp0[(size_t)NR_MAX * DM * DD];     // head: P in [d][c] layout (coalesced y dot)
__device__ float g_Wt1[(size_t)NR_MAX * DM * DD];     // tail: W^T [c][e], e=0 col unused
__device__ float g_off[2][NR_MAX * DD];               // mobius offset per relation
__device__ float g_off2[2][NR_MAX];                   // sum(off^2)
__device__ float g_p63[NR_MAX * DD];                  // tail: unscaled last col of P, [0]=0
__device__ float g_ofu[NR_MAX * DD];                  // tail: W @ off_sp, [0]=off0
__device__ float g_ttl[B_MAX * DD];                   // tail: W_t @ th_sp per b, [0]=0
__device__ float g_sc[B_MAX * 8];                     // {O2m,OTm,T2m,thb,th0,off0,off2,-}

__device__ __forceinline__ float gelu_exact(float x) {
    return 0.5f * x * (1.0f + erff(x * 0.70710678118654752f));
}

// block reduction over 64 threads (2 warps)
__device__ __forceinline__ float bred64(float v, volatile float* wsum, int lane, int wid) {
    #pragma unroll
    for (int o = 16; o; o >>= 1) v += __shfl_down_sync(0xffffffffu, v, o);
    if (lane == 0) wsum[wid] = v;
    __syncthreads();
    float r = wsum[0] + wsum[1];
    __syncthreads();
    return r;
}

// ============================================================================
// K0: fully-parallel gelu of all relation weights
// ============================================================================
__global__ void k_gelu(const float* __restrict__ Wh, const float* __restrict__ Wtt, int NR)
{
    int i = blockIdx.x * blockDim.x + threadIdx.x;
    int total = 2 * NR * DM * DD;
    if (i >= total) return;
    int k  = i & (DD - 1);
    int j  = (i >> 6) % DM;
    int rs = i / (DM * DD);
    int r  = rs % NR;
    int side = rs / NR;
    float v = 0.0f;
    if (k < DM) {
        const float* src = side ? Wtt : Wh;
        v = gelu_exact(src[(size_t)r * DM * DM + j * DM + k]);
    }
    g_Wg[side][(size_t)r * DM * DD + j * DD + k] = v;
}

// ============================================================================
// K1: per-relation precompute. grid (NR, 2), block 64.
//   Householder chain with wj register-cached via LDS.128 (reused dot+update).
// ============================================================================
__global__ void k_rel(const float* __restrict__ rch, const float* __restrict__ dirh,
                      const float* __restrict__ rct, const float* __restrict__ dirt,
                      const float* __restrict__ fsh, const float* __restrict__ fst)
{
    int r    = blockIdx.x;
    int side = blockIdx.y;
    const float* rc = side ? rct  : rch;
    const float* dw = side ? dirt : dirh;
    float fs        = side ? fst[0] : fsh[0];

    __shared__ __align__(16) float Wg[DM * DD];
    __shared__ float inv2s[DM];
    __shared__ float ws[DD];
    __shared__ float wsum[2];

    int tid = threadIdx.x;
    int lane = tid & 31, wid = tid >> 5;

    {
        const float4* src = (const float4*)&g_Wg[side][(size_t)r * DM * DD];
        float4* dst = (float4*)Wg;
        for (int i = tid; i < DM * DD / 4; i += 64) dst[i] = src[i];
    }
    __syncthreads();
    if (tid < DM) {
        const float* row = Wg + tid * DD;
        float s0 = 0, s1 = 0, s2 = 0, s3 = 0;
        #pragma unroll
        for (int k = 0; k < 60; k += 4) {
            s0 = fmaf(row[k    ], row[k    ], s0);
            s1 = fmaf(row[k + 1], row[k + 1], s1);
            s2 = fmaf(row[k + 2], row[k + 2], s2);
            s3 = fmaf(row[k + 3], row[k + 3], s3);
        }
        s0 = fmaf(row[60], row[60], s0);
        s1 = fmaf(row[61], row[61], s1);
        s2 = fmaf(row[62], row[62], s2);
        inv2s[tid] = 2.0f / ((s0 + s1) + (s2 + s3));
    }
    __syncthreads();

    float prow[DM];
    #pragma unroll
    for (int k = 0; k < DM; k++) prow[k] = (k == tid) ? 1.0f : 0.0f;

    for (int j = 0; j < DM; j++) {
        // cache wj in registers: 16 LDS.128, reused by dot AND update
        float wf[DD];
        const float4* wj4 = (const float4*)(Wg + j * DD);
        #pragma unroll
        for (int q = 0; q < 16; q++) *(float4*)&wf[4 * q] = wj4[q];

        float a0 = 0, a1 = 0, a2 = 0, a3 = 0;
        #pragma unroll
        for (int k = 0; k < 60; k += 4) {
            a0 = fmaf(prow[k    ], wf[k    ], a0);
            a1 = fmaf(prow[k + 1], wf[k + 1], a1);
            a2 = fmaf(prow[k + 2], wf[k + 2], a2);
            a3 = fmaf(prow[k + 3], wf[k + 3], a3);
        }
        a0 = fmaf(prow[60], wf[60], a0);
        a1 = fmaf(prow[61], wf[61], a1);
        a2 = fmaf(prow[62], wf[62], a2);
        float coef = ((a0 + a1) + (a2 + a3)) * inv2s[j];
        #pragma unroll
        for (int k = 0; k < DM; k++) prow[k] = fmaf(-coef, wf[k], prow[k]);
    }

    float p63v = prow[62];
    prow[62] *= fs;

    if (side == 0) {
        // [d][c] layout: thread tid owns row d=tid (coalesced reads in k_th)
        if (tid < DM) {
            float* base = &g_Wp0[(size_t)r * DM * DD + (size_t)tid * DD];
            #pragma unroll
            for (int c = 0; c < DM; c++) base[c] = prow[c];
        }
    } else {
        // [c][e] layout for t~ (coalesced per c)
        float* base = &g_Wt1[(size_t)r * DM * DD];
        if (tid < DM) {
            #pragma unroll
            for (int c = 0; c < DM; c++) base[(size_t)c * DD + 1 + tid] = prow[c];
        }
    }

    // ---- offset = expmap(c, 0.1 * normalize(d + <c,d> c)) ----
    float cv = rc[r * DD + tid];
    float dv = dw[r * DD + tid];
    float inner = bred64(cv * dv, wsum, lane, wid);
    float tv = fmaf(inner, cv, dv);
    float tn2 = bred64(tv * tv, wsum, lane, wid);
    tv = tv / (sqrtf(tn2) + 1e-6f);
    float uv = 0.1f * tv;
    float su2 = bred64(uv * uv, wsum, lane, wid);
    ws[tid] = uv;
    __syncthreads();
    float u0 = ws[0];
    float lin = su2 - 2.0f * u0 * u0;
    float nrm = fminf(sqrtf(fmaxf(lin, 1e-8f)), 2.5f);
    float off = coshf(nrm) * cv + sinhf(nrm) * uv / nrm;
    g_off[side][r * DD + tid] = off;
    float off2 = bred64(off * off, wsum, lane, wid);
    if (tid == 0) g_off2[side][r] = off2;

    if (side == 1) {
        __syncthreads();
        ws[tid] = off;
        __syncthreads();
        if (tid < DM) {
            float a0 = 0, a1 = 0, a2 = 0, a3 = 0;
            #pragma unroll
            for (int c = 0; c < 60; c += 4) {
                a0 = fmaf(prow[c    ], ws[c + 1], a0);
                a1 = fmaf(prow[c + 1], ws[c + 2], a1);
                a2 = fmaf(prow[c + 2], ws[c + 3], a2);
                a3 = fmaf(prow[c + 3], ws[c + 4], a3);
            }
            a0 = fmaf(prow[60], ws[61], a0);
            a1 = fmaf(prow[61], ws[62], a1);
            a2 = fmaf(prow[62], ws[63], a2);
            g_ofu[r * DD + 1 + tid] = (a0 + a1) + (a2 + a3);
            g_p63[r * DD + 1 + tid] = p63v;
        } else {
            g_ofu[r * DD] = ws[0];
            g_p63[r * DD] = 0.0f;
        }
    }
}

// ============================================================================
// K2: head transform + t~ + per-b scalar pack. grid B, block 64.
//   y matvec reads g_Wp0 [d][c] — coalesced (63 wavefronts vs 2048).
// ============================================================================
__global__ void k_th(const float* __restrict__ ent, const float* __restrict__ bias_head,
                     const int* __restrict__ u_idx, const int* __restrict__ r_idx)
{
    int b = blockIdx.x;
    int tid = threadIdx.x;
    int lane = tid & 31, wid = tid >> 5;
    __shared__ float xs[DD];
    __shared__ float ts[DD];
    __shared__ float wsum[2];
    int u = u_idx[b];
    int r = r_idx[b];
    xs[tid] = ent[(size_t)u * DD + tid];
    __syncthreads();

    float yv;
    if (tid == 0) {
        yv = xs[0];
    } else {
        const float* base0 = &g_Wp0[(size_t)r * DM * DD];  // [d][c]
        int c = tid - 1;
        float a0 = 0, a1 = 0, a2 = 0, a3 = 0;
        #pragma unroll 4
        for (int d = 0; d < 60; d += 4) {
            a0 = fmaf(xs[1 + d    ], base0[(d    ) * DD + c], a0);
            a1 = fmaf(xs[1 + d + 1], base0[(d + 1) * DD + c], a1);
            a2 = fmaf(xs[1 + d + 2], base0[(d + 2) * DD + c], a2);
            a3 = fmaf(xs[1 + d + 3], base0[(d + 3) * DD + c], a3);
        }
        a0 = fmaf(xs[61], base0[60 * DD + c], a0);
        a1 = fmaf(xs[62], base0[61 * DD + c], a1);
        a2 = fmaf(xs[63], base0[62 * DD + c], a2);
        yv = (a0 + a1) + (a2 + a3);
    }

    float offv = g_off[0][r * DD + tid];
    float x2 = bred64(yv * yv, wsum, lane, wid);
    float xy = bred64(yv * offv, wsum, lane, wid);
    float y2 = g_off2[0][r];
    float A   = 1.0f + 2.0f * xy + y2;
    float Bc  = 1.0f - x2;
    float den = 1.0f + 2.0f * xy + x2 * y2 + 1e-15f;
    float th  = fmaf(A, yv, Bc * offv) / den;

    ts[tid] = th;
    __syncthreads();

    // t~_d = sum_c W_t[d][c] * th_sp[c]  (coalesced per c)
    const float* base1 = &g_Wt1[(size_t)r * DM * DD];
    if (tid < DM) {
        float a0 = 0, a1 = 0, a2 = 0, a3 = 0;
        #pragma unroll 4
        for (int c = 0; c < 60; c += 4) {
            a0 = fmaf(base1[(c    ) * DD + 1 + tid], ts[c + 1], a0);
            a1 = fmaf(base1[(c + 1) * DD + 1 + tid], ts[c + 2], a1);
            a2 = fmaf(base1[(c + 2) * DD + 1 + tid], ts[c + 3], a2);
            a3 = fmaf(base1[(c + 3) * DD + 1 + tid], ts[c + 4], a3);
        }
        a0 = fmaf(base1[60 * DD + 1 + tid], ts[61], a0);
        a1 = fmaf(base1[61 * DD + 1 + tid], ts[62], a1);
        a2 = fmaf(base1[62 * DD + 1 + tid], ts[63], a2);
        g_ttl[b * DD + 1 + tid] = (a0 + a1) + (a2 + a3);
    } else {
        g_ttl[b * DD] = 0.0f;
    }

    // per-b scalars for k_main: O2m/OTm/T2m over c>=1 (tail off, th)
    float ot = g_off[1][r * DD + tid];
    float mo = (tid >= 1) ? ot : 0.0f;
    float mt = (tid >= 1) ? th : 0.0f;
    float O2m = bred64(mo * mo, wsum, lane, wid);
    float OTm = bred64(mo * mt, wsum, lane, wid);
    float T2m = bred64(mt * mt, wsum, lane, wid);
    if (tid == 0) {
        float* sc = &g_sc[b * 8];
        sc[0] = O2m;
        sc[1] = OTm;
        sc[2] = T2m;
        sc[3] = tanhf(bias_head[u]);
        sc[4] = th;          // th0
        sc[5] = ot;          // off0 (tail)
        sc[6] = g_off2[1][r];
        sc[7] = 0.0f;
    }
}

// ============================================================================
// K3: main scoring. grid (B, ceil(N/128)), block 128 — ONE tile per block.
//   Exposed latency overlaps across ~28 queued blocks/SM instead of
//   serializing across tiles inside a block. Prologue is 3 vector loads + 8
//   scalars (O2m etc. hoisted to k_th). bias_tail prefetched before gather.
// ============================================================================
__global__ void __launch_bounds__(TMAIN) k_main(
    const float* __restrict__ ent, const float* __restrict__ bias_tail,
    const int* __restrict__ r_idx, const int* __restrict__ v_idx,
    const float* __restrict__ fst,
    float* __restrict__ out, int N)
{
    __shared__ __align__(16) float xs[TILE * XSTR];   // 34816 B
    __shared__ int   vs[TILE];
    __shared__ float pv[DD], ov[DD], tl[DD];
    __shared__ float scs[8];

    int b     = blockIdx.x;
    int tbase = blockIdx.y * TILE;
    int tid   = threadIdx.x;
    if (tbase >= N) return;
    int nt = min(TILE, N - tbase);
    int r  = r_idx[b];

    if (tid < DD) {
        pv[tid] = g_p63[r * DD + tid];
        ov[tid] = g_ofu[r * DD + tid];
        tl[tid] = g_ttl[b * DD + tid];
    }
    if (tid < 8) scs[tid] = g_sc[b * 8 + tid];
    if (tid < TILE) vs[tid] = (tid < nt) ? v_idx[b * N + tbase + tid] : 0;
    float fsv  = fst[0];
    float fsm1 = fsv * fsv - 1.0f;
    __syncthreads();

    // prefetch scattered bias before the bulk gather (latency overlap)
    float btraw = bias_tail[vs[tid < nt ? tid : 0]];

    // gather: 16 consecutive lanes per ent row -> 4 lines per LDG.128
    #pragma unroll
    for (int i = 0; i < 16; i++) {
        int f  = i * TMAIN + tid;
        int tt = f >> 4;
        int q  = f & 15;
        const float4* src = (const float4*)(ent + (size_t)vs[tt] * DD) + q;
        *(float4*)&xs[tt * XSTR + q * 4] = *src;
    }
    __syncthreads();

    if (tid < nt) {
        const float4* xr  = (const float4*)&xs[tid * XSTR];
        const float4* pv4 = (const float4*)pv;
        const float4* ov4 = (const float4*)ov;
        const float4* tl4 = (const float4*)tl;

        float s1a = 0, s1b = 0, s2a = 0, s2b = 0, s3a = 0, s3b = 0;
        float y0 = xs[tid * XSTR];
        #pragma unroll
        for (int q = 0; q < 16; q++) {
            float4 x4 = xr[q];
            float4 p4 = pv4[q];
            float4 o4 = ov4[q];
            float4 t4 = tl4[q];
            s1a = fmaf(x4.x, p4.x, s1a);  s1b = fmaf(x4.y, p4.y, s1b);
            s1a = fmaf(x4.z, p4.z, s1a);  s1b = fmaf(x4.w, p4.w, s1b);
            s2a = fmaf(x4.x, o4.x, s2a);  s2b = fmaf(x4.y, o4.y, s2b);
            s2a = fmaf(x4.z, o4.z, s2a);  s2b = fmaf(x4.w, o4.w, s2b);
            s3a = fmaf(x4.x, t4.x, s3a);  s3b = fmaf(x4.y, t4.y, s3b);
            s3a = fmaf(x4.z, t4.z, s3a);  s3b = fmaf(x4.w, t4.w, s3b);
        }
        float s1  = s1a + s1b;          // x . p63
        float syo = s2a + s2b;          // includes x0*off0
        float syt = s3a + s3b;          // c>=1 only

        float O2m = scs[0], OTm = scs[1], T2m = scs[2], thb = scs[3];
        float th0 = scs[4], off0 = scs[5], off2 = scs[6];

        float syy_m = fmaf(fsm1, s1 * s1, fmaf(y0, y0, -1.0f));  // syy - y0^2
        float syy   = syy_m + y0 * y0;

        float A   = 1.0f + 2.0f * syo + off2;
        float Bv  = 1.0f - syy;
        float den = 1.0f + 2.0f * syo + syy * off2 + 1e-15f;
        float rd  = 1.0f / den;
        float a   = A * rd, bs = Bv * rd;
        float d0  = fmaf(a, y0, fmaf(bs, off0, -th0));
        float cross = fmaf(bs, syo - y0 * off0, -syt);
        float bterm = fmaf(bs, fmaf(bs, O2m, -2.0f * OTm), T2m);
        float sum1  = fmaf(a * a, syy_m, fmaf(2.0f * a, cross, bterm));
        float mkv   = sum1 - d0 * d0;

        out[(size_t)b * N + tbase + tid] = 8.0f - mkv + thb + tanhf(btraw);
    }
}

// ============================================================================
extern "C" void kernel_launch(void* const* d_in, const int* in_sizes, int n_in,
                              void* d_out, int out_size)
{
    (void)n_in; (void)out_size;
    const float* ent  = (const float*)d_in[0];
    const float* Wh   = (const float*)d_in[1];
    const float* Wtt  = (const float*)d_in[2];
    const float* rch  = (const float*)d_in[3];
    const float* dirh = (const float*)d_in[4];
    const float* rct  = (const float*)d_in[5];
    const float* dirt = (const float*)d_in[6];
    const float* bh   = (const float*)d_in[7];
    const float* bt   = (const float*)d_in[8];
    const float* fsh  = (const float*)d_in[9];
    const float* fst  = (const float*)d_in[10];
    const int* u_idx  = (const int*)d_in[11];
    const int* r_idx  = (const int*)d_in[12];
    const int* v_idx  = (const int*)d_in[13];
    float* out = (float*)d_out;

    int NR = in_sizes[3] / DD;       // 237
    int B  = in_sizes[11];           // 1024
    int N  = in_sizes[13] / B;       // 512
    int S  = (N + TILE - 1) / TILE;  // 4

    int total_g = 2 * NR * DM * DD;
    k_gelu<<<(total_g + 255) / 256, 256>>>(Wh, Wtt, NR);
    k_rel<<<dim3(NR, 2), 64>>>(rch, dirh, rct, dirt, fsh, fst);
    k_th<<<B, 64>>>(ent, bh, u_idx, r_idx);
    k_main<<<dim3(B, S), TMAIN>>>(ent, bt, r_idx, v_idx, fst, out, N);
}

// round 10
// speedup vs baseline: 1.3833x; 1.1521x over previous
#include <cuda_runtime.h>
#include <cstdint>
#include <cstddef>

#define DM 63
#define DD 64
#define NR_MAX 256
#define B_MAX 2048
#define TMAIN 128
#define TILE  128

// ---- scratch (static __device__ globals; no runtime allocation) ----
__device__ float g_Wg[2][(size_t)NR_MAX * DM * DD];   // gelu(W): [side][r][j][k], k=63 pad -> 0
__device__ float g_Wp0[(size_t)NR_MAX * DM * DD];     // head: P in [d][c] layout (coalesced y dot)
__device__ float g_Wt1[(size_t)NR_MAX * DM * DD];     // tail: W^T [c][e], e=0 col unused
__device__ float g_off[2][NR_MAX * DD];               // mobius offset per relation
__device__ float g_off2[2][NR_MAX];                   // sum(off^2)
__device__ float g_p63[NR_MAX * DD];                  // tail: unscaled last col of P, [0]=0
__device__ float g_ofu[NR_MAX * DD];                  // tail: W @ off_sp, [0]=off0
__device__ float g_ttl[B_MAX * DD];                   // tail: W_t @ th_sp per b, [0]=0
__device__ float g_sc[B_MAX * 8];                     // {O2m,OTm,T2m,thb,th0,off0,off2,-}

__device__ __forceinline__ float gelu_exact(float x) {
    return 0.5f * x * (1.0f + erff(x * 0.70710678118654752f));
}

// block reduction over 64 threads (2 warps)
__device__ __forceinline__ float bred64(float v, volatile float* wsum, int lane, int wid) {
    #pragma unroll
    for (int o = 16; o; o >>= 1) v += __shfl_down_sync(0xffffffffu, v, o);
    if (lane == 0) wsum[wid] = v;
    __syncthreads();
    float r = wsum[0] + wsum[1];
    __syncthreads();
    return r;
}

// ============================================================================
// K0: fully-parallel gelu of all relation weights
// ============================================================================
__global__ void k_gelu(const float* __restrict__ Wh, const float* __restrict__ Wtt, int NR)
{
    int i = blockIdx.x * blockDim.x + threadIdx.x;
    int total = 2 * NR * DM * DD;
    if (i >= total) return;
    int k  = i & (DD - 1);
    int j  = (i >> 6) % DM;
    int rs = i / (DM * DD);
    int r  = rs % NR;
    int side = rs / NR;
    float v = 0.0f;
    if (k < DM) {
        const float* src = side ? Wtt : Wh;
        v = gelu_exact(src[(size_t)r * DM * DM + j * DM + k]);
    }
    g_Wg[side][(size_t)r * DM * DD + j * DD + k] = v;
}

// ============================================================================
// K1: per-relation precompute. grid (NR, 2), block 64.
//   Householder chain; wj register-cached; dot at ILP-8 (serial critical path).
// ============================================================================
__global__ void k_rel(const float* __restrict__ rch, const float* __restrict__ dirh,
                      const float* __restrict__ rct, const float* __restrict__ dirt,
                      const float* __restrict__ fsh, const float* __restrict__ fst)
{
    int r    = blockIdx.x;
    int side = blockIdx.y;
    const float* rc = side ? rct  : rch;
    const float* dw = side ? dirt : dirh;
    float fs        = side ? fst[0] : fsh[0];

    __shared__ __align__(16) float Wg[DM * DD];
    __shared__ float inv2s[DM];
    __shared__ float ws[DD];
    __shared__ float wsum[2];

    int tid = threadIdx.x;
    int lane = tid & 31, wid = tid >> 5;

    {
        const float4* src = (const float4*)&g_Wg[side][(size_t)r * DM * DD];
        float4* dst = (float4*)Wg;
        for (int i = tid; i < DM * DD / 4; i += 64) dst[i] = src[i];
    }
    __syncthreads();
    if (tid < DM) {
        const float* row = Wg + tid * DD;
        float s0 = 0, s1 = 0, s2 = 0, s3 = 0;
        #pragma unroll
        for (int k = 0; k < 60; k += 4) {
            s0 = fmaf(row[k    ], row[k    ], s0);
            s1 = fmaf(row[k + 1], row[k + 1], s1);
            s2 = fmaf(row[k + 2], row[k + 2], s2);
            s3 = fmaf(row[k + 3], row[k + 3], s3);
        }
        s0 = fmaf(row[60], row[60], s0);
        s1 = fmaf(row[61], row[61], s1);
        s2 = fmaf(row[62], row[62], s2);
        inv2s[tid] = 2.0f / ((s0 + s1) + (s2 + s3));
    }
    __syncthreads();

    float prow[DM];
    #pragma unroll
    for (int k = 0; k < DM; k++) prow[k] = (k == tid) ? 1.0f : 0.0f;

    for (int j = 0; j < DM; j++) {
        // cache wj in registers: 16 LDS.128, reused by dot AND update
        float wf[DD];
        const float4* wj4 = (const float4*)(Wg + j * DD);
        #pragma unroll
        for (int q = 0; q < 16; q++) *(float4*)&wf[4 * q] = wj4[q];

        // ILP-8 dot (serial critical path of the chain)
        float a0 = 0, a1 = 0, a2 = 0, a3 = 0, a4 = 0, a5 = 0, a6 = 0, a7 = 0;
        #pragma unroll
        for (int k = 0; k < 56; k += 8) {
            a0 = fmaf(prow[k    ], wf[k    ], a0);
            a1 = fmaf(prow[k + 1], wf[k + 1], a1);
            a2 = fmaf(prow[k + 2], wf[k + 2], a2);
            a3 = fmaf(prow[k + 3], wf[k + 3], a3);
            a4 = fmaf(prow[k + 4], wf[k + 4], a4);
            a5 = fmaf(prow[k + 5], wf[k + 5], a5);
            a6 = fmaf(prow[k + 6], wf[k + 6], a6);
            a7 = fmaf(prow[k + 7], wf[k + 7], a7);
        }
        a0 = fmaf(prow[56], wf[56], a0);
        a1 = fmaf(prow[57], wf[57], a1);
        a2 = fmaf(prow[58], wf[58], a2);
        a3 = fmaf(prow[59], wf[59], a3);
        a4 = fmaf(prow[60], wf[60], a4);
        a5 = fmaf(prow[61], wf[61], a5);
        a6 = fmaf(prow[62], wf[62], a6);
        float coef = (((a0 + a1) + (a2 + a3)) + ((a4 + a5) + (a6 + a7))) * inv2s[j];
        #pragma unroll
        for (int k = 0; k < DM; k++) prow[k] = fmaf(-coef, wf[k], prow[k]);
    }

    float p63v = prow[62];
    prow[62] *= fs;

    if (side == 0) {
        if (tid < DM) {
            float* base = &g_Wp0[(size_t)r * DM * DD + (size_t)tid * DD];
            #pragma unroll
            for (int c = 0; c < DM; c++) base[c] = prow[c];
        }
    } else {
        float* base = &g_Wt1[(size_t)r * DM * DD];
        if (tid < DM) {
            #pragma unroll
            for (int c = 0; c < DM; c++) base[(size_t)c * DD + 1 + tid] = prow[c];
        }
    }

    // ---- offset = expmap(c, 0.1 * normalize(d + <c,d> c)) ----
    float cv = rc[r * DD + tid];
    float dv = dw[r * DD + tid];
    float inner = bred64(cv * dv, wsum, lane, wid);
    float tv = fmaf(inner, cv, dv);
    float tn2 = bred64(tv * tv, wsum, lane, wid);
    tv = tv / (sqrtf(tn2) + 1e-6f);
    float uv = 0.1f * tv;
    float su2 = bred64(uv * uv, wsum, lane, wid);
    ws[tid] = uv;
    __syncthreads();
    float u0 = ws[0];
    float lin = su2 - 2.0f * u0 * u0;
    float nrm = fminf(sqrtf(fmaxf(lin, 1e-8f)), 2.5f);
    float off = coshf(nrm) * cv + sinhf(nrm) * uv / nrm;
    g_off[side][r * DD + tid] = off;
    float off2 = bred64(off * off, wsum, lane, wid);
    if (tid == 0) g_off2[side][r] = off2;

    if (side == 1) {
        __syncthreads();
        ws[tid] = off;
        __syncthreads();
        if (tid < DM) {
            float a0 = 0, a1 = 0, a2 = 0, a3 = 0;
            #pragma unroll
            for (int c = 0; c < 60; c += 4) {
                a0 = fmaf(prow[c    ], ws[c + 1], a0);
                a1 = fmaf(prow[c + 1], ws[c + 2], a1);
                a2 = fmaf(prow[c + 2], ws[c + 3], a2);
                a3 = fmaf(prow[c + 3], ws[c + 4], a3);
            }
            a0 = fmaf(prow[60], ws[61], a0);
            a1 = fmaf(prow[61], ws[62], a1);
            a2 = fmaf(prow[62], ws[63], a2);
            g_ofu[r * DD + 1 + tid] = (a0 + a1) + (a2 + a3);
            g_p63[r * DD + 1 + tid] = p63v;
        } else {
            g_ofu[r * DD] = ws[0];
            g_p63[r * DD] = 0.0f;
        }
    }
}

// ============================================================================
// K2: head transform + t~ + per-b scalar pack. grid B, block 64.
// ============================================================================
__global__ void k_th(const float* __restrict__ ent, const float* __restrict__ bias_head,
                     const int* __restrict__ u_idx, const int* __restrict__ r_idx)
{
    int b = blockIdx.x;
    int tid = threadIdx.x;
    int lane = tid & 31, wid = tid >> 5;
    __shared__ float xs[DD];
    __shared__ float ts[DD];
    __shared__ float wsum[2];
    int u = u_idx[b];
    int r = r_idx[b];
    xs[tid] = ent[(size_t)u * DD + tid];
    __syncthreads();

    float yv;
    if (tid == 0) {
        yv = xs[0];
    } else {
        const float* base0 = &g_Wp0[(size_t)r * DM * DD];  // [d][c]
        int c = tid - 1;
        float a0 = 0, a1 = 0, a2 = 0, a3 = 0;
        #pragma unroll 4
        for (int d = 0; d < 60; d += 4) {
            a0 = fmaf(xs[1 + d    ], base0[(d    ) * DD + c], a0);
            a1 = fmaf(xs[1 + d + 1], base0[(d + 1) * DD + c], a1);
            a2 = fmaf(xs[1 + d + 2], base0[(d + 2) * DD + c], a2);
            a3 = fmaf(xs[1 + d + 3], base0[(d + 3) * DD + c], a3);
        }
        a0 = fmaf(xs[61], base0[60 * DD + c], a0);
        a1 = fmaf(xs[62], base0[61 * DD + c], a1);
        a2 = fmaf(xs[63], base0[62 * DD + c], a2);
        yv = (a0 + a1) + (a2 + a3);
    }

    float offv = g_off[0][r * DD + tid];
    float x2 = bred64(yv * yv, wsum, lane, wid);
    float xy = bred64(yv * offv, wsum, lane, wid);
    float y2 = g_off2[0][r];
    float A   = 1.0f + 2.0f * xy + y2;
    float Bc  = 1.0f - x2;
    float den = 1.0f + 2.0f * xy + x2 * y2 + 1e-15f;
    float th  = fmaf(A, yv, Bc * offv) / den;

    ts[tid] = th;
    __syncthreads();

    const float* base1 = &g_Wt1[(size_t)r * DM * DD];
    if (tid < DM) {
        float a0 = 0, a1 = 0, a2 = 0, a3 = 0;
        #pragma unroll 4
        for (int c = 0; c < 60; c += 4) {
            a0 = fmaf(base1[(c    ) * DD + 1 + tid], ts[c + 1], a0);
            a1 = fmaf(base1[(c + 1) * DD + 1 + tid], ts[c + 2], a1);
            a2 = fmaf(base1[(c + 2) * DD + 1 + tid], ts[c + 3], a2);
            a3 = fmaf(base1[(c + 3) * DD + 1 + tid], ts[c + 4], a3);
        }
        a0 = fmaf(base1[60 * DD + 1 + tid], ts[61], a0);
        a1 = fmaf(base1[61 * DD + 1 + tid], ts[62], a1);
        a2 = fmaf(base1[62 * DD + 1 + tid], ts[63], a2);
        g_ttl[b * DD + 1 + tid] = (a0 + a1) + (a2 + a3);
    } else {
        g_ttl[b * DD] = 0.0f;
    }

    float ot = g_off[1][r * DD + tid];
    float mo = (tid >= 1) ? ot : 0.0f;
    float mt = (tid >= 1) ? th : 0.0f;
    float O2m = bred64(mo * mo, wsum, lane, wid);
    float OTm = bred64(mo * mt, wsum, lane, wid);
    float T2m = bred64(mt * mt, wsum, lane, wid);
    if (tid == 0) {
        float* sc = &g_sc[b * 8];
        sc[0] = O2m;
        sc[1] = OTm;
        sc[2] = T2m;
        sc[3] = tanhf(bias_head[u]);
        sc[4] = th;          // th0
        sc[5] = ot;          // off0 (tail)
        sc[6] = g_off2[1][r];
        sc[7] = 0.0f;
    }
}

// ============================================================================
// K3: main scoring. grid (B, N/128), block 128. No x staging:
//   8 lanes own one ent row (lane h loads float4 h and h+8 -> each LDG.128 =
//   4 rows x 1 full 128B line = 4 wavefronts). Dots reduced via 3-step
//   shfl(width=8); lane h=0 (holds y0) writes {s1,syo,syt,y0} to smem; one
//   sync; per-thread epilogue. L1 traffic ~3x lower than staging version.
// ============================================================================
__global__ void __launch_bounds__(TMAIN) k_main(
    const float* __restrict__ ent, const float* __restrict__ bias_tail,
    const int* __restrict__ r_idx, const int* __restrict__ v_idx,
    const float* __restrict__ fst,
    float* __restrict__ out, int N)
{
    __shared__ __align__(16) float4 res4[TILE];
    __shared__ int   vs[TILE];
    __shared__ __align__(16) float pv[DD], ov[DD], tl[DD];
    __shared__ float scs[8];

    int b     = blockIdx.x;
    int tbase = blockIdx.y * TILE;
    int tid   = threadIdx.x;
    if (tbase >= N) return;
    int nt = min(TILE, N - tbase);
    int r  = r_idx[b];

    if (tid < DD) {
        pv[tid] = g_p63[r * DD + tid];
        ov[tid] = g_ofu[r * DD + tid];
        tl[tid] = g_ttl[b * DD + tid];
    }
    if (tid < 8) scs[tid] = g_sc[b * 8 + tid];
    vs[tid] = (tid < nt) ? v_idx[b * N + tbase + tid] : 0;
    float fsv  = fst[0];
    float fsm1 = fsv * fsv - 1.0f;
    __syncthreads();

    // prefetch scattered bias before the bulk gather (latency overlap)
    float btraw = bias_tail[vs[tid < nt ? tid : 0]];

    int h = tid & 7;          // lane within row-group
    int g = tid >> 3;         // row-slot 0..15 within block per iteration
    float4 pa = ((const float4*)pv)[h], pb = ((const float4*)pv)[h + 8];
    float4 oa = ((const float4*)ov)[h], ob = ((const float4*)ov)[h + 8];
    float4 ta = ((const float4*)tl)[h], tb = ((const float4*)tl)[h + 8];

    #pragma unroll
    for (int i = 0; i < 8; i++) {
        int row = i * 16 + g;                 // 0..127
        const float4* xr = (const float4*)(ent + (size_t)vs[row] * DD);
        float4 xa = xr[h];
        float4 xb = xr[h + 8];

        float s1 = fmaf(xa.x, pa.x, fmaf(xa.y, pa.y, fmaf(xa.z, pa.z, xa.w * pa.w)));
        s1 = fmaf(xb.x, pb.x, fmaf(xb.y, pb.y, fmaf(xb.z, pb.z, fmaf(xb.w, pb.w, s1))));
        float s2 = fmaf(xa.x, oa.x, fmaf(xa.y, oa.y, fmaf(xa.z, oa.z, xa.w * oa.w)));
        s2 = fmaf(xb.x, ob.x, fmaf(xb.y, ob.y, fmaf(xb.z, ob.z, fmaf(xb.w, ob.w, s2))));
        float s3 = fmaf(xa.x, ta.x, fmaf(xa.y, ta.y, fmaf(xa.z, ta.z, xa.w * ta.w)));
        s3 = fmaf(xb.x, tb.x, fmaf(xb.y, tb.y, fmaf(xb.z, tb.z, fmaf(xb.w, tb.w, s3))));

        #pragma unroll
        for (int o = 4; o; o >>= 1) {
            s1 += __shfl_down_sync(0xffffffffu, s1, o, 8);
            s2 += __shfl_down_sync(0xffffffffu, s2, o, 8);
            s3 += __shfl_down_sync(0xffffffffu, s3, o, 8);
        }
        if (h == 0) res4[row] = make_float4(s1, s2, s3, xa.x);  // xa.x = x[0] = y0
    }
    __syncthreads();

    if (tid < nt) {
        float4 rr = res4[tid];
        float s1 = rr.x, syo = rr.y, syt = rr.z, y0 = rr.w;

        float O2m = scs[0], OTm = scs[1], T2m = scs[2], thb = scs[3];
        float th0 = scs[4], off0 = scs[5], off2 = scs[6];

        float syy_m = fmaf(fsm1, s1 * s1, fmaf(y0, y0, -1.0f));  // syy - y0^2
        float syy   = syy_m + y0 * y0;

        float A   = 1.0f + 2.0f * syo + off2;
        float Bv  = 1.0f - syy;
        float den = 1.0f + 2.0f * syo + syy * off2 + 1e-15f;
        float rd  = 1.0f / den;
        float a   = A * rd, bs = Bv * rd;
        float d0  = fmaf(a, y0, fmaf(bs, off0, -th0));
        float cross = fmaf(bs, syo - y0 * off0, -syt);
        float bterm = fmaf(bs, fmaf(bs, O2m, -2.0f * OTm), T2m);
        float sum1  = fmaf(a * a, syy_m, fmaf(2.0f * a, cross, bterm));
        float mkv   = sum1 - d0 * d0;

        out[(size_t)b * N + tbase + tid] = 8.0f - mkv + thb + tanhf(btraw);
    }
}

// ============================================================================
extern "C" void kernel_launch(void* const* d_in, const int* in_sizes, int n_in,
                              void* d_out, int out_size)
{
    (void)n_in; (void)out_size;
    const float* ent  = (const float*)d_in[0];
    const float* Wh   = (const float*)d_in[1];
    const float* Wtt  = (const float*)d_in[2];
    const float* rch  = (const float*)d_in[3];
    const float* dirh = (const float*)d_in[4];
    const float* rct  = (const float*)d_in[5];
    const float* dirt = (const float*)d_in[6];
    const float* bh   = (const float*)d_in[7];
    const float* bt   = (const float*)d_in[8];
    const float* fsh  = (const float*)d_in[9];
    const float* fst  = (const float*)d_in[10];
    const int* u_idx  = (const int*)d_in[11];
    const int* r_idx  = (const int*)d_in[12];
    const int* v_idx  = (const int*)d_in[13];
    float* out = (float*)d_out;

    int NR = in_sizes[3] / DD;       // 237
    int B  = in_sizes[11];           // 1024
    int N  = in_sizes[13] / B;       // 512
    int S  = (N + TILE - 1) / TILE;  // 4

    int total_g = 2 * NR * DM * DD;
    k_gelu<<<(total_g + 255) / 256, 256>>>(Wh, Wtt, NR);
    k_rel<<<dim3(NR, 2), 64>>>(rch, dirh, rct, dirt, fsh, fst);
    k_th<<<B, 64>>>(ent, bh, u_idx, r_idx);
    k_main<<<dim3(B, S), TMAIN>>>(ent, bt, r_idx, v_idx, fst, out, N);
}

// round 11
// speedup vs baseline: 1.4492x; 1.0477x over previous
#include <cuda_runtime.h>
#include <cstdint>
#include <cstddef>

#define DM 63
#define DD 64
#define NR_MAX 256
#define B_MAX 2048
#define TMAIN 128
#define TILE  128
#define TSTR  65   // transpose staging stride (conflict-free both ways)

// ---- scratch (static __device__ globals; no runtime allocation) ----
__device__ float g_Wg[2][(size_t)NR_MAX * DM * DD];   // gelu(W): [side][r][j][k], k=63 pad -> 0
__device__ float g_Wp0[(size_t)NR_MAX * DM * DD];     // head: P in [d][c] layout (coalesced y dot)
__device__ float g_Wt1[(size_t)NR_MAX * DM * DD];     // tail: W^T [c][e], e=0 col unused
__device__ float g_off[2][NR_MAX * DD];               // mobius offset per relation
__device__ float g_off2[2][NR_MAX];                   // sum(off^2)
__device__ float g_p63[NR_MAX * DD];                  // tail: unscaled last col of P, [0]=0
__device__ float g_ofu[NR_MAX * DD];                  // tail: W @ off_sp, [0]=off0
__device__ float g_ttl[B_MAX * DD];                   // tail: W_t @ th_sp per b, [0]=0
__device__ float g_sc[B_MAX * 8];                     // {O2m,OTm,T2m,thb,th0,off0,off2,-}

__device__ __forceinline__ float gelu_exact(float x) {
    return 0.5f * x * (1.0f + erff(x * 0.70710678118654752f));
}

// block reduction over 64 threads (2 warps)
__device__ __forceinline__ float bred64(float v, volatile float* wsum, int lane, int wid) {
    #pragma unroll
    for (int o = 16; o; o >>= 1) v += __shfl_down_sync(0xffffffffu, v, o);
    if (lane == 0) wsum[wid] = v;
    __syncthreads();
    float r = wsum[0] + wsum[1];
    __syncthreads();
    return r;
}

// ============================================================================
// K0: fully-parallel gelu of all relation weights
// ============================================================================
__global__ void k_gelu(const float* __restrict__ Wh, const float* __restrict__ Wtt, int NR)
{
    int i = blockIdx.x * blockDim.x + threadIdx.x;
    int total = 2 * NR * DM * DD;
    if (i >= total) return;
    int k  = i & (DD - 1);
    int j  = (i >> 6) % DM;
    int rs = i / (DM * DD);
    int r  = rs % NR;
    int side = rs / NR;
    float v = 0.0f;
    if (k < DM) {
        const float* src = side ? Wtt : Wh;
        v = gelu_exact(src[(size_t)r * DM * DM + j * DM + k]);
    }
    g_Wg[side][(size_t)r * DM * DD + j * DD + k] = v;
}

// ============================================================================
// K1: per-relation precompute. grid (NR, 2), block 64.
//   Rank-2 Householder steps (31 pairs + 1 single): chain latency halved.
//   Side-0 store goes through a stride-65 shared transpose (coalesced STG).
// ============================================================================
__global__ void k_rel(const float* __restrict__ rch, const float* __restrict__ dirh,
                      const float* __restrict__ rct, const float* __restrict__ dirt,
                      const float* __restrict__ fsh, const float* __restrict__ fst)
{
    int r    = blockIdx.x;
    int side = blockIdx.y;
    const float* rc = side ? rct  : rch;
    const float* dw = side ? dirt : dirh;
    float fs        = side ? fst[0] : fsh[0];

    __shared__ __align__(16) float Wg[DM * DD];
    __shared__ float Ts[DM * TSTR];       // transpose staging (side 0)
    __shared__ float inv2s[DM];
    __shared__ float g12s[32];            // w_{2j} . w_{2j+1}
    __shared__ float ws[DD];
    __shared__ float wsum[2];

    int tid = threadIdx.x;
    int lane = tid & 31, wid = tid >> 5;

    {
        const float4* src = (const float4*)&g_Wg[side][(size_t)r * DM * DD];
        float4* dst = (float4*)Wg;
        for (int i = tid; i < DM * DD / 4; i += 64) dst[i] = src[i];
    }
    __syncthreads();
    if (tid < DM) {
        const float* row = Wg + tid * DD;
        float s0 = 0, s1 = 0, s2 = 0, s3 = 0;
        #pragma unroll
        for (int k = 0; k < 60; k += 4) {
            s0 = fmaf(row[k    ], row[k    ], s0);
            s1 = fmaf(row[k + 1], row[k + 1], s1);
            s2 = fmaf(row[k + 2], row[k + 2], s2);
            s3 = fmaf(row[k + 3], row[k + 3], s3);
        }
        s0 = fmaf(row[60], row[60], s0);
        s1 = fmaf(row[61], row[61], s1);
        s2 = fmaf(row[62], row[62], s2);
        inv2s[tid] = 2.0f / ((s0 + s1) + (s2 + s3));
    }
    // cross inner products for pairs (2j, 2j+1)
    if (tid < 31) {
        const float* ra = Wg + (2 * tid) * DD;
        const float* rb = Wg + (2 * tid + 1) * DD;
        float s0 = 0, s1 = 0, s2 = 0, s3 = 0;
        #pragma unroll
        for (int k = 0; k < 60; k += 4) {
            s0 = fmaf(ra[k    ], rb[k    ], s0);
            s1 = fmaf(ra[k + 1], rb[k + 1], s1);
            s2 = fmaf(ra[k + 2], rb[k + 2], s2);
            s3 = fmaf(ra[k + 3], rb[k + 3], s3);
        }
        s0 = fmaf(ra[60], rb[60], s0);
        s1 = fmaf(ra[61], rb[61], s1);
        s2 = fmaf(ra[62], rb[62], s2);
        g12s[tid] = (s0 + s1) + (s2 + s3);
    }
    __syncthreads();

    float prow[DM];
    #pragma unroll
    for (int k = 0; k < DM; k++) prow[k] = (k == tid) ? 1.0f : 0.0f;

    // 31 rank-2 steps
    for (int j = 0; j < 62; j += 2) {
        const float* w2 = Wg + (j + 1) * DD;
        float wf[DD];                     // w1 register-cached (used twice)
        const float4* wj4 = (const float4*)(Wg + j * DD);
        #pragma unroll
        for (int q = 0; q < 16; q++) *(float4*)&wf[4 * q] = wj4[q];

        float a0 = 0, a1 = 0, a2 = 0, a3 = 0;   // d1 = p . w1
        float b0 = 0, b1 = 0, b2 = 0, b3 = 0;   // e2 = p . w2
        #pragma unroll
        for (int k = 0; k < 60; k += 4) {
            a0 = fmaf(prow[k    ], wf[k    ], a0);
            a1 = fmaf(prow[k + 1], wf[k + 1], a1);
            a2 = fmaf(prow[k + 2], wf[k + 2], a2);
            a3 = fmaf(prow[k + 3], wf[k + 3], a3);
            b0 = fmaf(prow[k    ], w2[k    ], b0);
            b1 = fmaf(prow[k + 1], w2[k + 1], b1);
            b2 = fmaf(prow[k + 2], w2[k + 2], b2);
            b3 = fmaf(prow[k + 3], w2[k + 3], b3);
        }
        a0 = fmaf(prow[60], wf[60], a0);
        a1 = fmaf(prow[61], wf[61], a1);
        a2 = fmaf(prow[62], wf[62], a2);
        b0 = fmaf(prow[60], w2[60], b0);
        b1 = fmaf(prow[61], w2[61], b1);
        b2 = fmaf(prow[62], w2[62], b2);
        float d1 = (a0 + a1) + (a2 + a3);
        float e2 = (b0 + b1) + (b2 + b3);
        float c1 = d1 * inv2s[j];
        float c2 = fmaf(-c1, g12s[j >> 1], e2) * inv2s[j + 1];
        #pragma unroll
        for (int k = 0; k < DM; k++)
            prow[k] = fmaf(-c2, w2[k], fmaf(-c1, wf[k], prow[k]));
    }
    // final single step j = 62
    {
        const float* w3 = Wg + 62 * DD;
        float a0 = 0, a1 = 0, a2 = 0, a3 = 0;
        #pragma unroll
        for (int k = 0; k < 60; k += 4) {
            a0 = fmaf(prow[k    ], w3[k    ], a0);
            a1 = fmaf(prow[k + 1], w3[k + 1], a1);
            a2 = fmaf(prow[k + 2], w3[k + 2], a2);
            a3 = fmaf(prow[k + 3], w3[k + 3], a3);
        }
        a0 = fmaf(prow[60], w3[60], a0);
        a1 = fmaf(prow[61], w3[61], a1);
        a2 = fmaf(prow[62], w3[62], a2);
        float coef = ((a0 + a1) + (a2 + a3)) * inv2s[62];
        #pragma unroll
        for (int k = 0; k < DM; k++) prow[k] = fmaf(-coef, w3[k], prow[k]);
    }

    float p63v = prow[62];
    prow[62] *= fs;

    if (side == 0) {
        // transpose via stride-65 staging -> coalesced row-wise STG
        if (tid < DM) {
            #pragma unroll
            for (int c = 0; c < DM; c++) Ts[tid + TSTR * c] = prow[c];
        }
        __syncthreads();
        float* base = &g_Wp0[(size_t)r * DM * DD];
        if (tid < DM) {
            #pragma unroll 1
            for (int d = 0; d < DM; d++) base[d * DD + tid] = Ts[d + TSTR * tid];
        }
    } else {
        float* base = &g_Wt1[(size_t)r * DM * DD];
        if (tid < DM) {
            #pragma unroll
            for (int c = 0; c < DM; c++) base[(size_t)c * DD + 1 + tid] = prow[c];
        }
    }

    // ---- offset = expmap(c, 0.1 * normalize(d + <c,d> c)) ----
    __syncthreads();
    float cv = rc[r * DD + tid];
    float dv = dw[r * DD + tid];
    float inner = bred64(cv * dv, wsum, lane, wid);
    float tv = fmaf(inner, cv, dv);
    float tn2 = bred64(tv * tv, wsum, lane, wid);
    tv = tv / (sqrtf(tn2) + 1e-6f);
    float uv = 0.1f * tv;
    float su2 = bred64(uv * uv, wsum, lane, wid);
    ws[tid] = uv;
    __syncthreads();
    float u0 = ws[0];
    float lin = su2 - 2.0f * u0 * u0;
    float nrm = fminf(sqrtf(fmaxf(lin, 1e-8f)), 2.5f);
    float off = coshf(nrm) * cv + sinhf(nrm) * uv / nrm;
    g_off[side][r * DD + tid] = off;
    float off2 = bred64(off * off, wsum, lane, wid);
    if (tid == 0) g_off2[side][r] = off2;

    if (side == 1) {
        __syncthreads();
        ws[tid] = off;
        __syncthreads();
        if (tid < DM) {
            float a0 = 0, a1 = 0, a2 = 0, a3 = 0;
            #pragma unroll
            for (int c = 0; c < 60; c += 4) {
                a0 = fmaf(prow[c    ], ws[c + 1], a0);
                a1 = fmaf(prow[c + 1], ws[c + 2], a1);
                a2 = fmaf(prow[c + 2], ws[c + 3], a2);
                a3 = fmaf(prow[c + 3], ws[c + 4], a3);
            }
            a0 = fmaf(prow[60], ws[61], a0);
            a1 = fmaf(prow[61], ws[62], a1);
            a2 = fmaf(prow[62], ws[63], a2);
            g_ofu[r * DD + 1 + tid] = (a0 + a1) + (a2 + a3);
            g_p63[r * DD + 1 + tid] = p63v;
        } else {
            g_ofu[r * DD] = ws[0];
            g_p63[r * DD] = 0.0f;
        }
    }
}

// ============================================================================
// K2: head transform + t~ + per-b scalar pack. grid B, block 64.
// ============================================================================
__global__ void k_th(const float* __restrict__ ent, const float* __restrict__ bias_head,
                     const int* __restrict__ u_idx, const int* __restrict__ r_idx)
{
    int b = blockIdx.x;
    int tid = threadIdx.x;
    int lane = tid & 31, wid = tid >> 5;
    __shared__ float xs[DD];
    __shared__ float ts[DD];
    __shared__ float wsum[2];
    int u = u_idx[b];
    int r = r_idx[b];
    xs[tid] = ent[(size_t)u * DD + tid];
    __syncthreads();

    float yv;
    if (tid == 0) {
        yv = xs[0];
    } else {
        const float* base0 = &g_Wp0[(size_t)r * DM * DD];  // [d][c]
        int c = tid - 1;
        float a0 = 0, a1 = 0, a2 = 0, a3 = 0;
        #pragma unroll 4
        for (int d = 0; d < 60; d += 4) {
            a0 = fmaf(xs[1 + d    ], base0[(d    ) * DD + c], a0);
            a1 = fmaf(xs[1 + d + 1], base0[(d + 1) * DD + c], a1);
            a2 = fmaf(xs[1 + d + 2], base0[(d + 2) * DD + c], a2);
            a3 = fmaf(xs[1 + d + 3], base0[(d + 3) * DD + c], a3);
        }
        a0 = fmaf(xs[61], base0[60 * DD + c], a0);
        a1 = fmaf(xs[62], base0[61 * DD + c], a1);
        a2 = fmaf(xs[63], base0[62 * DD + c], a2);
        yv = (a0 + a1) + (a2 + a3);
    }

    float offv = g_off[0][r * DD + tid];
    float x2 = bred64(yv * yv, wsum, lane, wid);
    float xy = bred64(yv * offv, wsum, lane, wid);
    float y2 = g_off2[0][r];
    float A   = 1.0f + 2.0f * xy + y2;
    float Bc  = 1.0f - x2;
    float den = 1.0f + 2.0f * xy + x2 * y2 + 1e-15f;
    float th  = fmaf(A, yv, Bc * offv) / den;

    ts[tid] = th;
    __syncthreads();

    const float* base1 = &g_Wt1[(size_t)r * DM * DD];
    if (tid < DM) {
        float a0 = 0, a1 = 0, a2 = 0, a3 = 0;
        #pragma unroll 4
        for (int c = 0; c < 60; c += 4) {
            a0 = fmaf(base1[(c    ) * DD + 1 + tid], ts[c + 1], a0);
            a1 = fmaf(base1[(c + 1) * DD + 1 + tid], ts[c + 2], a1);
            a2 = fmaf(base1[(c + 2) * DD + 1 + tid], ts[c + 3], a2);
            a3 = fmaf(base1[(c + 3) * DD + 1 + tid], ts[c + 4], a3);
        }
        a0 = fmaf(base1[60 * DD + 1 + tid], ts[61], a0);
        a1 = fmaf(base1[61 * DD + 1 + tid], ts[62], a1);
        a2 = fmaf(base1[62 * DD + 1 + tid], ts[63], a2);
        g_ttl[b * DD + 1 + tid] = (a0 + a1) + (a2 + a3);
    } else {
        g_ttl[b * DD] = 0.0f;
    }

    float ot = g_off[1][r * DD + tid];
    float mo = (tid >= 1) ? ot : 0.0f;
    float mt = (tid >= 1) ? th : 0.0f;
    float O2m = bred64(mo * mo, wsum, lane, wid);
    float OTm = bred64(mo * mt, wsum, lane, wid);
    float T2m = bred64(mt * mt, wsum, lane, wid);
    if (tid == 0) {
        float* sc = &g_sc[b * 8];
        sc[0] = O2m;
        sc[1] = OTm;
        sc[2] = T2m;
        sc[3] = tanhf(bias_head[u]);
        sc[4] = th;          // th0
        sc[5] = ot;          // off0 (tail)
        sc[6] = g_off2[1][r];
        sc[7] = 0.0f;
    }
}

// ============================================================================
// K3: main scoring. grid (B, N/128), block 128. No x staging:
//   8 lanes own one ent row; dots reduced via shfl(width=8); lane h=0 writes
//   {s1,syo,syt,y0} to smem; one sync; per-thread epilogue.
// ============================================================================
__global__ void __launch_bounds__(TMAIN) k_main(
    const float* __restrict__ ent, const float* __restrict__ bias_tail,
    const int* __restrict__ r_idx, const int* __restrict__ v_idx,
    const float* __restrict__ fst,
    float* __restrict__ out, int N)
{
    __shared__ __align__(16) float4 res4[TILE];
    __shared__ int   vs[TILE];
    __shared__ __align__(16) float pv[DD], ov[DD], tl[DD];
    __shared__ float scs[8];

    int b     = blockIdx.x;
    int tbase = blockIdx.y * TILE;
    int tid   = threadIdx.x;
    if (tbase >= N) return;
    int nt = min(TILE, N - tbase);
    int r  = r_idx[b];

    if (tid < DD) {
        pv[tid] = g_p63[r * DD + tid];
        ov[tid] = g_ofu[r * DD + tid];
        tl[tid] = g_ttl[b * DD + tid];
    }
    if (tid < 8) scs[tid] = g_sc[b * 8 + tid];
    vs[tid] = (tid < nt) ? v_idx[b * N + tbase + tid] : 0;
    float fsv  = fst[0];
    float fsm1 = fsv * fsv - 1.0f;
    __syncthreads();

    // prefetch scattered bias before the bulk gather (latency overlap)
    float btraw = bias_tail[vs[tid < nt ? tid : 0]];

    int h = tid & 7;          // lane within row-group
    int g = tid >> 3;         // row-slot 0..15 within block per iteration
    float4 pa = ((const float4*)pv)[h], pb = ((const float4*)pv)[h + 8];
    float4 oa = ((const float4*)ov)[h], ob = ((const float4*)ov)[h + 8];
    float4 ta = ((const float4*)tl)[h], tb = ((const float4*)tl)[h + 8];

    #pragma unroll
    for (int i = 0; i < 8; i++) {
        int row = i * 16 + g;                 // 0..127
        const float4* xr = (const float4*)(ent + (size_t)vs[row] * DD);
        float4 xa = xr[h];
        float4 xb = xr[h + 8];

        float s1 = fmaf(xa.x, pa.x, fmaf(xa.y, pa.y, fmaf(xa.z, pa.z, xa.w * pa.w)));
        s1 = fmaf(xb.x, pb.x, fmaf(xb.y, pb.y, fmaf(xb.z, pb.z, fmaf(xb.w, pb.w, s1))));
        float s2 = fmaf(xa.x, oa.x, fmaf(xa.y, oa.y, fmaf(xa.z, oa.z, xa.w * oa.w)));
        s2 = fmaf(xb.x, ob.x, fmaf(xb.y, ob.y, fmaf(xb.z, ob.z, fmaf(xb.w, ob.w, s2))));
        float s3 = fmaf(xa.x, ta.x, fmaf(xa.y, ta.y, fmaf(xa.z, ta.z, xa.w * ta.w)));
        s3 = fmaf(xb.x, tb.x, fmaf(xb.y, tb.y, fmaf(xb.z, tb.z, fmaf(xb.w, tb.w, s3))));

        #pragma unroll
        for (int o = 4; o; o >>= 1) {
            s1 += __shfl_down_sync(0xffffffffu, s1, o, 8);
            s2 += __shfl_down_sync(0xffffffffu, s2, o, 8);
            s3 += __shfl_down_sync(0xffffffffu, s3, o, 8);
        }
        if (h == 0) res4[row] = make_float4(s1, s2, s3, xa.x);  // xa.x = x[0] = y0
    }
    __syncthreads();

    if (tid < nt) {
        float4 rr = res4[tid];
        float s1 = rr.x, syo = rr.y, syt = rr.z, y0 = rr.w;

        float O2m = scs[0], OTm = scs[1], T2m = scs[2], thb = scs[3];
        float th0 = scs[4], off0 = scs[5], off2 = scs[6];

        float syy_m = fmaf(fsm1, s1 * s1, fmaf(y0, y0, -1.0f));  // syy - y0^2
        float syy   = syy_m + y0 * y0;

        float A   = 1.0f + 2.0f * syo + off2;
        float Bv  = 1.0f - syy;
        float den = 1.0f + 2.0f * syo + syy * off2 + 1e-15f;
        float rd  = 1.0f / den;
        float a   = A * rd, bs = Bv * rd;
        float d0  = fmaf(a, y0, fmaf(bs, off0, -th0));
        float cross = fmaf(bs, syo - y0 * off0, -syt);
        float bterm = fmaf(bs, fmaf(bs, O2m, -2.0f * OTm), T2m);
        float sum1  = fmaf(a * a, syy_m, fmaf(2.0f * a, cross, bterm));
        float mkv   = sum1 - d0 * d0;

        out[(size_t)b * N + tbase + tid] = 8.0f - mkv + thb + tanhf(btraw);
    }
}

// ============================================================================
extern "C" void kernel_launch(void* const* d_in, const int* in_sizes, int n_in,
                              void* d_out, int out_size)
{
    (void)n_in; (void)out_size;
    const float* ent  = (const float*)d_in[0];
    const float* Wh   = (const float*)d_in[1];
    const float* Wtt  = (const float*)d_in[2];
    const float* rch  = (const float*)d_in[3];
    const float* dirh = (const float*)d_in[4];
    const float* rct  = (const float*)d_in[5];
    const float* dirt = (const float*)d_in[6];
    const float* bh   = (const float*)d_in[7];
    const float* bt   = (const float*)d_in[8];
    const float* fsh  = (const float*)d_in[9];
    const float* fst  = (const float*)d_in[10];
    const int* u_idx  = (const int*)d_in[11];
    const int* r_idx  = (const int*)d_in[12];
    const int* v_idx  = (const int*)d_in[13];
    float* out = (float*)d_out;

    int NR = in_sizes[3] / DD;       // 237
    int B  = in_sizes[11];           // 1024
    int N  = in_sizes[13] / B;       // 512
    int S  = (N + TILE - 1) / TILE;  // 4

    int total_g = 2 * NR * DM * DD;
    k_gelu<<<(total_g + 255) / 256, 256>>>(Wh, Wtt, NR);
    k_rel<<<dim3(NR, 2), 64>>>(rch, dirh, rct, dirt, fsh, fst);
    k_th<<<B, 64>>>(ent, bh, u_idx, r_idx);
    k_main<<<dim3(B, S), TMAIN>>>(ent, bt, r_idx, v_idx, fst, out, N);
}

// round 13
// speedup vs baseline: 1.6778x; 1.1577x over previous
#include <cuda_runtime.h>
#include <cstdint>
#include <cstddef>

#define DM 63
#define DD 64
#define NR_MAX 256
#define B_MAX 2048
#define TMAIN 128
#define TILE  128
#define WSTR  65   // smem row stride (conflict-free row-major dots)

// ---- scratch (static __device__ globals; no runtime allocation) ----
__device__ float g_Wg[2][(size_t)NR_MAX * DD * DD];   // gelu(W) rows [j*64+k], row 63 zeroed
__device__ float g_iv[2][NR_MAX * DD];                // 2/s_j (j=63 -> 0)
__device__ float g_G [2][NR_MAX * 224];               // intra-segment Gram pairs
__device__ float g_off[2][NR_MAX * DD];               // mobius offset per relation
__device__ float g_off2[2][NR_MAX];                   // sum(off^2)
__device__ float g_p63[NR_MAX * DD];                  // tail: P e62 (unscaled last col), [0]=0
__device__ float g_ofu[NR_MAX * DD];                  // tail: P D off_sp, [0]=off0
__device__ float g_ttl[B_MAX * DD];                   // tail: P D th_sp per b, [0]=0
__device__ float g_sc[B_MAX * 8];                     // {O2m,OTm,T2m,thb,th0,off0,off2,-}

__device__ __constant__ int c_pa[28] = {0,0,1,0,1,2,0,1,2,3,0,1,2,3,4,0,1,2,3,4,5,0,1,2,3,4,5,6};
__device__ __constant__ int c_pb[28] = {1,2,2,3,3,3,4,4,4,4,5,5,5,5,5,6,6,6,6,6,6,7,7,7,7,7,7,7};

__device__ __forceinline__ float gelu_exact(float x) {
    return 0.5f * x * (1.0f + erff(x * 0.70710678118654752f));
}

// block reduction over 64 threads (2 warps)
__device__ __forceinline__ float bred64(float v, volatile float* wsum, int lane, int wid) {
    #pragma unroll
    for (int o = 16; o; o >>= 1) v += __shfl_down_sync(0xffffffffu, v, o);
    if (lane == 0) wsum[wid] = v;
    __syncthreads();
    float r = wsum[0] + wsum[1];
    __syncthreads();
    return r;
}

// ============================================================================
// Rank-8 reflection segment applied to a warp-held vector.
// Layout: lane l owns full-vec comps l (slot0) and l+32 (slot1); chain comp c
// lives at full idx c+1 (lane0 slot0 = time comp, excluded via w0=0).
// FWD: applied order i=0..7 (y = H1..H63 x). REV: i=7..0 (P v).
// Pad: reflection 63 has w=0, iv=0 -> c=0, no-op.
// ============================================================================
template<bool FWD>
__device__ __forceinline__ void apply_seg(
    float& v0, float& v1, int lane,
    const float* __restrict__ W, int wstride,
    const float* __restrict__ iv, const float* __restrict__ G, int seg)
{
    int lo = seg * 8;
    float w0[8], w1[8], d[8], ivv[8], g[28];
    #pragma unroll
    for (int i = 0; i < 8; i++) {
        const float* row = W + (size_t)(lo + i) * wstride;
        w0[i] = (lane >= 1) ? row[lane - 1] : 0.0f;
        w1[i] = row[lane + 31];
        ivv[i] = iv[lo + i];
    }
    #pragma unroll
    for (int p = 0; p < 28; p++) g[p] = G[seg * 28 + p];
    #pragma unroll
    for (int i = 0; i < 8; i++) d[i] = fmaf(w0[i], v0, w1[i] * v1);
    #pragma unroll
    for (int o = 16; o; o >>= 1) {
        #pragma unroll
        for (int i = 0; i < 8; i++) d[i] += __shfl_xor_sync(0xffffffffu, d[i], o);
    }
    float c[8];
    if (FWD) {
        c[0] = d[0] * ivv[0];
        c[1] = (d[1] - c[0]*g[0]) * ivv[1];
        c[2] = (d[2] - c[0]*g[1] - c[1]*g[2]) * ivv[2];
        c[3] = (d[3] - c[0]*g[3] - c[1]*g[4] - c[2]*g[5]) * ivv[3];
        c[4] = (d[4] - c[0]*g[6] - c[1]*g[7] - c[2]*g[8] - c[3]*g[9]) * ivv[4];
        c[5] = (d[5] - c[0]*g[10] - c[1]*g[11] - c[2]*g[12] - c[3]*g[13] - c[4]*g[14]) * ivv[5];
        c[6] = (d[6] - c[0]*g[15] - c[1]*g[16] - c[2]*g[17] - c[3]*g[18] - c[4]*g[19] - c[5]*g[20]) * ivv[6];
        c[7] = (d[7] - c[0]*g[21] - c[1]*g[22] - c[2]*g[23] - c[3]*g[24] - c[4]*g[25] - c[5]*g[26] - c[6]*g[27]) * ivv[7];
    } else {
        c[7] = d[7] * ivv[7];
        c[6] = (d[6] - c[7]*g[27]) * ivv[6];
        c[5] = (d[5] - c[7]*g[26] - c[6]*g[20]) * ivv[5];
        c[4] = (d[4] - c[7]*g[25] - c[6]*g[19] - c[5]*g[14]) * ivv[4];
        c[3] = (d[3] - c[7]*g[24] - c[6]*g[18] - c[5]*g[13] - c[4]*g[9]) * ivv[3];
        c[2] = (d[2] - c[7]*g[23] - c[6]*g[17] - c[5]*g[12] - c[4]*g[8] - c[3]*g[5]) * ivv[2];
        c[1] = (d[1] - c[7]*g[22] - c[6]*g[16] - c[5]*g[11] - c[4]*g[7] - c[3]*g[4] - c[2]*g[2]) * ivv[1];
        c[0] = (d[0] - c[7]*g[21] - c[6]*g[15] - c[5]*g[10] - c[4]*g[6] - c[3]*g[3] - c[2]*g[1] - c[1]*g[0]) * ivv[0];
    }
    float s0 = 0.0f, s1 = 0.0f;
    #pragma unroll
    for (int i = 0; i < 8; i++) { s0 = fmaf(c[i], w0[i], s0); s1 = fmaf(c[i], w1[i], s1); }
    v0 -= s0; v1 -= s1;
}

// ============================================================================
// K1: per-relation precompute. grid (NR, 2), block 64.
//   gelu (fused) + inv2s + intra-segment Gram + expmap offsets; side1 also
//   runs the õ and p63 reverse chains (one warp each).
// ============================================================================
__global__ void k_rel(const float* __restrict__ Wh,  const float* __restrict__ Wtt,
                      const float* __restrict__ rch, const float* __restrict__ dirh,
                      const float* __restrict__ rct, const float* __restrict__ dirt,
                      const float* __restrict__ fsh, const float* __restrict__ fst)
{
    int r    = blockIdx.x;
    int side = blockIdx.y;
    const float* Wemb = side ? Wtt  : Wh;
    const float* rc   = side ? rct  : rch;
    const float* dw   = side ? dirt : dirh;
    float fs          = side ? fst[0] : fsh[0];

    __shared__ float WgS[DD * WSTR];
    __shared__ float ivS[DD];
    __shared__ float GS[224];
    __shared__ float offS[DD];
    __shared__ float ws[DD];
    __shared__ float wsum[2];

    int tid = threadIdx.x, lane = tid & 31, wid = tid >> 5;
    float* gW = &g_Wg[side][(size_t)r * DD * DD];

    // zero pad row 63 (smem + global)
    for (int k = tid; k < WSTR; k += 64) WgS[63 * WSTR + k] = 0.0f;
    for (int k = tid; k < DD;   k += 64) gW[63 * DD + k]    = 0.0f;

    // gelu all 63x63 weights -> smem (stride 65) + global (stride 64)
    const float* wb = Wemb + (size_t)r * DM * DM;
    for (int idx = tid; idx < DM * DM; idx += 64) {
        int j = idx / DM, k = idx - j * DM;
        float v = gelu_exact(wb[idx]);
        WgS[j * WSTR + k] = v;
        gW[j * DD + k]    = v;
    }
    __syncthreads();

    // inv2s = 2 / ||w_j||^2  (row 63 pad -> 0)
    if (tid < DM) {
        const float* row = WgS + tid * WSTR;
        float s0 = 0, s1 = 0, s2 = 0, s3 = 0;
        #pragma unroll
        for (int k = 0; k < 60; k += 4) {
            s0 = fmaf(row[k    ], row[k    ], s0);
            s1 = fmaf(row[k + 1], row[k + 1], s1);
            s2 = fmaf(row[k + 2], row[k + 2], s2);
            s3 = fmaf(row[k + 3], row[k + 3], s3);
        }
        s0 = fmaf(row[60], row[60], s0);
        s1 = fmaf(row[61], row[61], s1);
        s2 = fmaf(row[62], row[62], s2);
        float ivv = 2.0f / ((s0 + s1) + (s2 + s3));
        ivS[tid] = ivv;
        g_iv[side][r * DD + tid] = ivv;
    } else {
        ivS[tid] = 0.0f;
        g_iv[side][r * DD + tid] = 0.0f;
    }

    // intra-segment Gram pairs (8 segs x 28; seg7 pairs hit row63=0 -> 0)
    for (int idx = tid; idx < 224; idx += 64) {
        int s = idx / 28, p = idx - s * 28;
        const float* ra = WgS + (s * 8 + c_pa[p]) * WSTR;
        const float* rb = WgS + (s * 8 + c_pb[p]) * WSTR;
        float a0 = 0, a1 = 0, a2 = 0, a3 = 0;
        #pragma unroll
        for (int k = 0; k < 60; k += 4) {
            a0 = fmaf(ra[k    ], rb[k    ], a0);
            a1 = fmaf(ra[k + 1], rb[k + 1], a1);
            a2 = fmaf(ra[k + 2], rb[k + 2], a2);
            a3 = fmaf(ra[k + 3], rb[k + 3], a3);
        }
        a0 = fmaf(ra[60], rb[60], a0);
        a1 = fmaf(ra[61], rb[61], a1);
        a2 = fmaf(ra[62], rb[62], a2);
        float gv = (a0 + a1) + (a2 + a3);
        GS[idx] = gv;
        g_G[side][r * 224 + idx] = gv;
    }

    // ---- offset = expmap(c, 0.1 * normalize(d + <c,d> c)) ----
    float cv = rc[r * DD + tid];
    float dv = dw[r * DD + tid];
    float inner = bred64(cv * dv, wsum, lane, wid);
    float tv = fmaf(inner, cv, dv);
    float tn2 = bred64(tv * tv, wsum, lane, wid);
    tv = tv / (sqrtf(tn2) + 1e-6f);
    float uv = 0.1f * tv;
    float su2 = bred64(uv * uv, wsum, lane, wid);
    ws[tid] = uv;
    __syncthreads();
    float u0 = ws[0];
    float lin = su2 - 2.0f * u0 * u0;
    float nrm = fminf(sqrtf(fmaxf(lin, 1e-8f)), 2.5f);
    float off = coshf(nrm) * cv + sinhf(nrm) * uv / nrm;
    g_off[side][r * DD + tid] = off;
    float off2 = bred64(off * off, wsum, lane, wid);
    if (tid == 0) g_off2[side][r] = off2;

    offS[tid] = off;
    __syncthreads();

    if (side == 1) {
        if (wid == 0) {
            // õ = P D off_sp : reverse chain on (flip-scaled) offset spatial part
            float v0 = (lane >= 1) ? offS[lane] : 0.0f;
            float v1 = offS[lane + 32];
            if (lane == 31) v1 *= fs;
            #pragma unroll 1
            for (int s = 7; s >= 0; s--) apply_seg<false>(v0, v1, lane, WgS, WSTR, ivS, GS, s);
            if (lane == 0) g_ofu[r * DD] = offS[0];
            else           g_ofu[r * DD + lane] = v0;
            g_ofu[r * DD + lane + 32] = v1;
        } else {
            // p63 = P e62 : reverse chain on unit vector (no flip)
            float v0 = 0.0f;
            float v1 = (lane == 31) ? 1.0f : 0.0f;
            #pragma unroll 1
            for (int s = 7; s >= 0; s--) apply_seg<false>(v0, v1, lane, WgS, WSTR, ivS, GS, s);
            g_p63[r * DD + lane] = (lane >= 1) ? v0 : 0.0f;
            g_p63[r * DD + lane + 32] = v1;
        }
    }
}

// ============================================================================
// K2: per-batch-row head pipeline. grid B, ONE warp.
//   head chain (fwd) -> mobius -> tail chain (rev) on th -> t~ + scalar pack.
// ============================================================================
__global__ void __launch_bounds__(32) k_head(
    const float* __restrict__ ent, const float* __restrict__ bias_head,
    const int* __restrict__ u_idx, const int* __restrict__ r_idx,
    const float* __restrict__ fsh, const float* __restrict__ fst)
{
    int b = blockIdx.x, l = threadIdx.x;
    int u = u_idx[b], r = r_idx[b];
    float fsH = fsh[0], fsT = fst[0];

    float v0 = ent[(size_t)u * DD + l];
    float v1 = ent[(size_t)u * DD + l + 32];

    {   // y_sp = D (P^T x_sp): apply H1..H63 (forward), then flip comp62
        const float* W  = &g_Wg[0][(size_t)r * DD * DD];
        const float* iv = &g_iv[0][r * DD];
        const float* G  = &g_G[0][r * 224];
        #pragma unroll 1
        for (int s = 0; s < 8; s++) apply_seg<true>(v0, v1, l, W, DD, iv, G, s);
    }
    if (l == 31) v1 *= fsH;

    // mobius_add(y, off_h)
    float oh0 = g_off[0][r * DD + l];
    float oh1 = g_off[0][r * DD + l + 32];
    float x2 = fmaf(v0, v0, v1 * v1);
    float xy = fmaf(v0, oh0, v1 * oh1);
    #pragma unroll
    for (int o = 16; o; o >>= 1) {
        x2 += __shfl_xor_sync(0xffffffffu, x2, o);
        xy += __shfl_xor_sync(0xffffffffu, xy, o);
    }
    float y2  = g_off2[0][r];
    float A   = 1.0f + 2.0f * xy + y2;
    float Bc  = 1.0f - x2;
    float den = 1.0f + 2.0f * xy + x2 * y2 + 1e-15f;
    float rd  = 1.0f / den;
    float th0c = fmaf(A, v0, Bc * oh0) * rd;
    float th1c = fmaf(A, v1, Bc * oh1) * rd;

    // t~ = P D th_sp : flip-scale comp62, then reverse chain (time untouched)
    float t0 = th0c, t1 = th1c;
    if (l == 31) t1 *= fsT;
    {
        const float* W  = &g_Wg[1][(size_t)r * DD * DD];
        const float* iv = &g_iv[1][r * DD];
        const float* G  = &g_G[1][r * 224];
        #pragma unroll 1
        for (int s = 7; s >= 0; s--) apply_seg<false>(t0, t1, l, W, DD, iv, G, s);
    }
    g_ttl[b * DD + l]      = (l >= 1) ? t0 : 0.0f;
    g_ttl[b * DD + l + 32] = t1;

    // scalar pack: O2m/OTm/T2m over spatial comps (exclude time at lane0 slot0)
    float ot0 = g_off[1][r * DD + l];
    float ot1 = g_off[1][r * DD + l + 32];
    float e0  = (l >= 1) ? 1.0f : 0.0f;
    float pO2 = fmaf(e0 * ot0, ot0,  ot1 * ot1);
    float pOT = fmaf(e0 * ot0, th0c, ot1 * th1c);
    float pT2 = fmaf(e0 * th0c, th0c, th1c * th1c);
    #pragma unroll
    for (int o = 16; o; o >>= 1) {
        pO2 += __shfl_xor_sync(0xffffffffu, pO2, o);
        pOT += __shfl_xor_sync(0xffffffffu, pOT, o);
        pT2 += __shfl_xor_sync(0xffffffffu, pT2, o);
    }
    if (l == 0) {
        float* sc = &g_sc[b * 8];
        sc[0] = pO2;
        sc[1] = pOT;
        sc[2] = pT2;
        sc[3] = tanhf(bias_head[u]);
        sc[4] = th0c;            // th0 (time)
        sc[5] = ot0;             // off0 (tail, time)
        sc[6] = g_off2[1][r];
        sc[7] = 0.0f;
    }
}

// ============================================================================
// K3: main scoring (unchanged from R11). grid (B, N/128), block 128.
// ============================================================================
__global__ void __launch_bounds__(TMAIN) k_main(
    const float* __restrict__ ent, const float* __restrict__ bias_tail,
    const int* __restrict__ r_idx, const int* __restrict__ v_idx,
    const float* __restrict__ fst,
    float* __restrict__ out, int N)
{
    __shared__ __align__(16) float4 res4[TILE];
    __shared__ int   vs[TILE];
    __shared__ __align__(16) float pv[DD], ov[DD], tl[DD];
    __shared__ float scs[8];

    int b     = blockIdx.x;
    int tbase = blockIdx.y * TILE;
    int tid   = threadIdx.x;
    if (tbase >= N) return;
    int nt = min(TILE, N - tbase);
    int r  = r_idx[b];

    if (tid < DD) {
        pv[tid] = g_p63[r * DD + tid];
        ov[tid] = g_ofu[r * DD + tid];
        tl[tid] = g_ttl[b * DD + tid];
    }
    if (tid < 8) scs[tid] = g_sc[b * 8 + tid];
    vs[tid] = (tid < nt) ? v_idx[b * N + tbase + tid] : 0;
    float fsv  = fst[0];
    float fsm1 = fsv * fsv - 1.0f;
    __syncthreads();

    float btraw = bias_tail[vs[tid < nt ? tid : 0]];

    int h = tid & 7;
    int g = tid >> 3;
    float4 pa = ((const float4*)pv)[h], pb = ((const float4*)pv)[h + 8];
    float4 oa = ((const float4*)ov)[h], ob = ((const float4*)ov)[h + 8];
    float4 ta = ((const float4*)tl)[h], tb = ((const float4*)tl)[h + 8];

    #pragma unroll
    for (int i = 0; i < 8; i++) {
        int row = i * 16 + g;
        const float4* xr = (const float4*)(ent + (size_t)vs[row] * DD);
        float4 xa = xr[h];
        float4 xb = xr[h + 8];

        float s1 = fmaf(xa.x, pa.x, fmaf(xa.y, pa.y, fmaf(xa.z, pa.z, xa.w * pa.w)));
        s1 = fmaf(xb.x, pb.x, fmaf(xb.y, pb.y, fmaf(xb.z, pb.z, fmaf(xb.w, pb.w, s1))));
        float s2 = fmaf(xa.x, oa.x, fmaf(xa.y, oa.y, fmaf(xa.z, oa.z, xa.w * oa.w)));
        s2 = fmaf(xb.x, ob.x, fmaf(xb.y, ob.y, fmaf(xb.z, ob.z, fmaf(xb.w, ob.w, s2))));
        float s3 = fmaf(xa.x, ta.x, fmaf(xa.y, ta.y, fmaf(xa.z, ta.z, xa.w * ta.w)));
        s3 = fmaf(xb.x, tb.x, fmaf(xb.y, tb.y, fmaf(xb.z, tb.z, fmaf(xb.w, tb.w, s3))));

        #pragma unroll
        for (int o = 4; o; o >>= 1) {
            s1 += __shfl_down_sync(0xffffffffu, s1, o, 8);
            s2 += __shfl_down_sync(0xffffffffu, s2, o, 8);
            s3 += __shfl_down_sync(0xffffffffu, s3, o, 8);
        }
        if (h == 0) res4[row] = make_float4(s1, s2, s3, xa.x);
    }
    __syncthreads();

    if (tid < nt) {
        float4 rr = res4[tid];
        float s1 = rr.x, syo = rr.y, syt = rr.z, y0 = rr.w;

        float O2m = scs[0], OTm = scs[1], T2m = scs[2], thb = scs[3];
        float th0 = scs[4], off0 = scs[5], off2 = scs[6];

        float syy_m = fmaf(fsm1, s1 * s1, fmaf(y0, y0, -1.0f));
        float syy   = syy_m + y0 * y0;

        float A   = 1.0f + 2.0f * syo + off2;
        float Bv  = 1.0f - syy;
        float den = 1.0f + 2.0f * syo + syy * off2 + 1e-15f;
        float rd  = 1.0f / den;
        float a   = A * rd, bs = Bv * rd;
        float d0  = fmaf(a, y0, fmaf(bs, off0, -th0));
        float cross = fmaf(bs, syo - y0 * off0, -syt);
        float bterm = fmaf(bs, fmaf(bs, O2m, -2.0f * OTm), T2m);
        float sum1  = fmaf(a * a, syy_m, fmaf(2.0f * a, cross, bterm));
        float mkv   = sum1 - d0 * d0;

        out[(size_t)b * N + tbase + tid] = 8.0f - mkv + thb + tanhf(btraw);
    }
}

// ============================================================================
extern "C" void kernel_launch(void* const* d_in, const int* in_sizes, int n_in,
                              void* d_out, int out_size)
{
    (void)n_in; (void)out_size;
    const float* ent  = (const float*)d_in[0];
    const float* Wh   = (const float*)d_in[1];
    const float* Wtt  = (const float*)d_in[2];
    const float* rch  = (const float*)d_in[3];
    const float* dirh = (const float*)d_in[4];
    const float* rct  = (const float*)d_in[5];
    const float* dirt = (const float*)d_in[6];
    const float* bh   = (const float*)d_in[7];
    const float* bt   = (const float*)d_in[8];
    const float* fsh  = (const float*)d_in[9];
    const float* fst  = (const float*)d_in[10];
    const int* u_idx  = (const int*)d_in[11];
    const int* r_idx  = (const int*)d_in[12];
    const int* v_idx  = (const int*)d_in[13];
    float* out = (float*)d_out;

    int NR = in_sizes[3] / DD;       // 237
    int B  = in_sizes[11];           // 1024
    int N  = in_sizes[13] / B;       // 512
    int S  = (N + TILE - 1) / TILE;  // 4

    k_rel<<<dim3(NR, 2), 64>>>(Wh, Wtt, rch, dirh, rct, dirt, fsh, fst);
    k_head<<<B, 32>>>(ent, bh, u_idx, r_idx, fsh, fst);
    k_main<<<dim3(B, S), TMAIN>>>(ent, bt, r_idx, v_idx, fst, out, N);
}